// round 13
// baseline (speedup 1.0000x reference)
#include <cuda_runtime.h>
#include <cuda_fp16.h>
#include <cstdint>

// ---------------------------------------------------------------- constants
#define BATCH 4
#define SEQ   2048
#define DMODEL 512
#define NHEAD 8
#define HDIM  64
#define MROWS 8192
#define QKV_N 1536

// ---------------------------------------------------------------- scratch (fp16)
__device__ __half g_xf[(size_t)MROWS * DMODEL];
__device__ __half g_wqf[(size_t)DMODEL * QKV_N];
__device__ __half g_wof[(size_t)DMODEL * DMODEL];
__device__ __half g_qf[(size_t)BATCH * NHEAD * SEQ * HDIM];
__device__ __half g_kf[(size_t)BATCH * NHEAD * SEQ * HDIM];
__device__ __half g_vf[(size_t)BATCH * NHEAD * SEQ * HDIM];
__device__ __half g_aof[(size_t)MROWS * DMODEL];

// ---------------------------------------------------------------- helpers
__device__ __forceinline__ uint32_t smem_u32(const void* p) {
    uint32_t a;
    asm("{ .reg .u64 t; cvta.to.shared.u64 t, %1; cvt.u32.u64 %0, t; }"
        : "=r"(a) : "l"(p));
    return a;
}
__device__ __forceinline__ void ldm_x4(uint32_t* r, uint32_t addr) {
    asm volatile("ldmatrix.sync.aligned.m8n8.x4.shared.b16 {%0,%1,%2,%3}, [%4];"
                 : "=r"(r[0]), "=r"(r[1]), "=r"(r[2]), "=r"(r[3]) : "r"(addr));
}
__device__ __forceinline__ void ldm_x4_t(uint32_t* r, uint32_t addr) {
    asm volatile("ldmatrix.sync.aligned.m8n8.x4.trans.shared.b16 {%0,%1,%2,%3}, [%4];"
                 : "=r"(r[0]), "=r"(r[1]), "=r"(r[2]), "=r"(r[3]) : "r"(addr));
}
__device__ __forceinline__ void mma16816h(float* d, const uint32_t* a, const uint32_t* b) {
    asm volatile(
        "mma.sync.aligned.m16n8k16.row.col.f32.f16.f16.f32 "
        "{%0,%1,%2,%3}, {%4,%5,%6,%7}, {%8,%9}, {%0,%1,%2,%3};"
        : "+f"(d[0]), "+f"(d[1]), "+f"(d[2]), "+f"(d[3])
        : "r"(a[0]), "r"(a[1]), "r"(a[2]), "r"(a[3]), "r"(b[0]), "r"(b[1]));
}
__device__ __forceinline__ uint32_t pack_f16(float a, float b) {
    __half2 h = __floats2half2_rn(a, b);
    return *reinterpret_cast<uint32_t*>(&h);
}
__device__ __forceinline__ float ex2f(float x) {
    float r;
    asm("ex2.approx.f32 %0, %1;" : "=f"(r) : "f"(x));
    return r;
}

#define CP16(dst, src) \
    asm volatile("cp.async.cg.shared.global [%0], [%1], 16;" :: "r"(dst), "l"(src))
#define CP_COMMIT() asm volatile("cp.async.commit_group;" ::: "memory")
#define CP_WAIT(n)  asm volatile("cp.async.wait_group %0;" :: "n"(n) : "memory")

// Q scale with log2(e) folded in: scores come out in log2 domain.
#define QSCALE (0.125f * 1.4426950408889634f)

// ---------------------------------------------------------------- fused convert fp32 -> fp16
#define N4_X  (MROWS * DMODEL / 4)
#define N4_WQ (DMODEL * QKV_N / 4)
#define N4_WO (DMODEL * DMODEL / 4)
#define N4_TOT (N4_X + N4_WQ + N4_WO)
__global__ __launch_bounds__(256)
void convert_all(const float4* __restrict__ x, const float4* __restrict__ wq,
                 const float4* __restrict__ wo) {
    const int i = blockIdx.x * 256 + threadIdx.x;
    if (i >= N4_TOT) return;
    const float4* src;
    uint2* dst;
    int j = i;
    if (j < N4_X) { src = x; dst = (uint2*)g_xf; }
    else if ((j -= N4_X) < N4_WQ) { src = wq; dst = (uint2*)g_wqf; }
    else { j -= N4_WQ; src = wo; dst = (uint2*)g_wof; }
    float4 v = src[j];
    uint2 o;
    o.x = pack_f16(v.x, v.y);
    o.y = pack_f16(v.z, v.w);
    dst[j] = o;
}

// ---------------------------------------------------------------- GEMM (fp16 HMMA)
// BM=128 BN=128 BK=32, 8 warps (4m x 2n), warp tile 32x64. 3-stage cp.async.
// Stage (18944 B): A[128x40h]@0, B[32x136h]@10240.
#define GSTG 18944
template <int MODE>
__global__ __launch_bounds__(256, 2)
void gemm_f16(const __half* __restrict__ A, const __half* __restrict__ B,
              const float* __restrict__ bias, float* __restrict__ C, int N) {
    extern __shared__ char sm[];
    const uint32_t sbase = smem_u32(sm);
    const int tid = threadIdx.x, lane = tid & 31, w = tid >> 5;
    const int wm = w >> 1, wn = w & 1;
    const int m0 = blockIdx.y * 128, n0 = blockIdx.x * 128;

    float acc[2][8][4];
#pragma unroll
    for (int i = 0; i < 2; i++)
#pragma unroll
        for (int j = 0; j < 8; j++)
#pragma unroll
            for (int e = 0; e < 4; e++) acc[i][j][e] = 0.f;

    const int q0 = tid * 2;
    const int ar0 = q0 >> 2, ac0 = q0 & 3;
    const int ar1 = (q0 + 1) >> 2, ac1 = (q0 + 1) & 3;
    const int br0 = q0 >> 4, bc0 = q0 & 15;
    const int br1 = (q0 + 1) >> 4, bc1 = (q0 + 1) & 15;

    auto issue = [&](int kt) {
        const uint32_t base = sbase + (kt % 3) * GSTG;
        CP16(base + ar0 * 80 + ac0 * 16, A + (size_t)(m0 + ar0) * 512 + kt * 32 + ac0 * 8);
        CP16(base + ar1 * 80 + ac1 * 16, A + (size_t)(m0 + ar1) * 512 + kt * 32 + ac1 * 8);
        CP16(base + 10240 + br0 * 272 + bc0 * 16, B + (size_t)(kt * 32 + br0) * N + n0 + bc0 * 8);
        CP16(base + 10240 + br1 * 272 + bc1 * 16, B + (size_t)(kt * 32 + br1) * N + n0 + bc1 * 8);
        CP_COMMIT();
    };

    issue(0);
    issue(1);
    for (int kt = 0; kt < 16; kt++) {
        CP_WAIT(1);
        __syncthreads();
        if (kt + 2 < 16) issue(kt + 2);
        const uint32_t bA = sbase + (kt % 3) * GSTG;
#pragma unroll
        for (int ks = 0; ks < 2; ks++) {
            uint32_t ah[2][4];
#pragma unroll
            for (int mf = 0; mf < 2; mf++) {
                const uint32_t ra = bA +
                    ((wm * 32 + mf * 16 + (lane & 15)) * 40 + ks * 16 + (lane >> 4) * 8) * 2;
                ldm_x4(ah[mf], ra);
            }
            uint32_t bh[4][4];
#pragma unroll
            for (int g = 0; g < 4; g++) {
                const uint32_t rb = bA + 10240 +
                    ((ks * 16 + (lane & 15)) * 136 + wn * 64 + g * 16 + (lane >> 4) * 8) * 2;
                ldm_x4_t(bh[g], rb);
            }
#pragma unroll
            for (int mf = 0; mf < 2; mf++)
#pragma unroll
                for (int nf = 0; nf < 8; nf++) {
                    const int g = nf >> 1, o = (nf & 1) * 2;
                    uint32_t bf[2] = {bh[g][o], bh[g][o + 1]};
                    mma16816h(acc[mf][nf], ah[mf], bf);
                }
        }
    }

    // epilogue
#pragma unroll
    for (int mf = 0; mf < 2; mf++)
#pragma unroll
        for (int nf = 0; nf < 8; nf++) {
            const int col = n0 + wn * 64 + nf * 8 + (lane & 3) * 2;
            const float b0 = bias[col], b1 = bias[col + 1];
#pragma unroll
            for (int rr = 0; rr < 2; rr++) {
                const int row = m0 + wm * 32 + mf * 16 + (lane >> 2) + rr * 8;
                float v0 = acc[mf][nf][rr * 2] + b0;
                float v1 = acc[mf][nf][rr * 2 + 1] + b1;
                if (MODE == 0) {
                    const int part = col >> 9, ww = col & 511;
                    const int h = ww >> 6, hd = ww & 63;
                    const int bb = row >> 11, sidx = row & 2047;
                    if (part == 0) { v0 *= QSCALE; v1 *= QSCALE; }
                    __half* df = (part == 0) ? g_qf : (part == 1) ? g_kf : g_vf;
                    const size_t idx =
                        ((((size_t)bb * NHEAD + h) * SEQ) + sidx) * HDIM + hd;
                    *reinterpret_cast<uint32_t*>(df + idx) = pack_f16(v0, v1);
                } else {
                    *reinterpret_cast<float2*>(C + (size_t)row * N + col) =
                        make_float2(v0, v1);
                }
            }
        }
}

// ---------------------------------------------------------------- attention (fp16 HMMA)
// 256 threads (8 warps), q-block = 128 rows, grid (8, 32) = 256 CTAs,
// 2 CTAs/SM. CTA p handles q-blocks {p, 15-p} -> exactly 34 k-block iters.
// Triple-buffered KV ring, ONE __syncthreads per k-block, log2-domain softmax.
// Smem: Q@0 (128x72h = 18432 B); KV stage s @ 18432+s*18432 (K@+0, V@+9216).
// Total 73728 B -> two CTAs fit in 228KB.
__global__ __launch_bounds__(256, 2)
void attn_mma() {
    extern __shared__ char sm[];
    const uint32_t sbase = smem_u32(sm);
    const int tid = threadIdx.x, lane = tid & 31, w = tid >> 5;
    const int p = blockIdx.x, bh = blockIdx.y;

    const size_t hbase = (size_t)bh * SEQ * HDIM;
    const int qlist[2] = {p, 15 - p};

    auto issueKV = [&](int kb) {
        const uint32_t base = sbase + 18432 + (kb % 3) * 18432;
        const int k0 = kb * 64;
        const int row = tid >> 2, c = tid & 3;   // 256 thr: 64 rows x 4 chunk-pairs
        CP16(base + row * 144 + c * 32, g_kf + hbase + (size_t)(k0 + row) * 64 + c * 16);
        CP16(base + row * 144 + c * 32 + 16, g_kf + hbase + (size_t)(k0 + row) * 64 + c * 16 + 8);
        CP16(base + 9216 + row * 144 + c * 32, g_vf + hbase + (size_t)(k0 + row) * 64 + c * 16);
        CP16(base + 9216 + row * 144 + c * 32 + 16, g_vf + hbase + (size_t)(k0 + row) * 64 + c * 16 + 8);
        CP_COMMIT();
    };

    for (int qq = 0; qq < 2; qq++) {
        const int qb = qlist[qq];
        const __half* Qf = g_qf + hbase + (size_t)qb * 128 * HDIM;

        __syncthreads();   // guard Q smem rewrite vs previous qq readers
#pragma unroll
        for (int t = 0; t < 4; t++) {
            const int q = tid * 4 + t;           // 0..1023 (128 rows x 8 chunks)
            const int row = q >> 3, c = q & 7;
            CP16(sbase + row * 144 + c * 16, Qf + (size_t)row * 64 + c * 8);
        }
        CP_COMMIT();

        const int nkb = 2 * qb + 2;
        issueKV(0);

        float oacc[8][4];
#pragma unroll
        for (int j = 0; j < 8; j++)
#pragma unroll
            for (int e = 0; e < 4; e++) oacc[j][e] = 0.f;
        float mrow[2] = {-1e30f, -1e30f};
        float lrow[2] = {0.f, 0.f};
        const int qi0 = qb * 128 + w * 16 + (lane >> 2);

        for (int kb = 0; kb < nkb; kb++) {
            const int k0 = kb * 64;
            if (kb + 1 < nkb) { issueKV(kb + 1); CP_WAIT(1); }
            else CP_WAIT(0);
            __syncthreads();   // single sync per iteration (3-buffer ring)
            const uint32_t kvb = sbase + 18432 + (kb % 3) * 18432;

            if (qb * 128 + w * 16 + 15 >= k0) {
                // ---- S = Q K^T (log2-domain scores)
                float sacc[8][4];
#pragma unroll
                for (int j = 0; j < 8; j++)
#pragma unroll
                    for (int e = 0; e < 4; e++) sacc[j][e] = 0.f;
#pragma unroll
                for (int ks = 0; ks < 4; ks++) {
                    uint32_t qf[4];
                    const uint32_t ra = sbase +
                        ((w * 16 + (lane & 15)) * 72 + ks * 16 + (lane >> 4) * 8) * 2;
                    ldm_x4(qf, ra);
                    uint32_t kf[4][4];
#pragma unroll
                    for (int g = 0; g < 4; g++) {
                        const uint32_t rb = kvb +
                            ((g * 16 + (lane & 15)) * 72 + ks * 16 + (lane >> 4) * 8) * 2;
                        ldm_x4(kf[g], rb);
                    }
#pragma unroll
                    for (int nf = 0; nf < 8; nf++) {
                        const int g = nf >> 1, o = nf & 1;
                        uint32_t bf[2] = {kf[g][o], kf[g][o + 2]};
                        mma16816h(sacc[nf], qf, bf);
                    }
                }
                // ---- online softmax (ex2-domain)
                float mx[2] = {-1e30f, -1e30f};
                if (k0 + 63 <= qi0) {
#pragma unroll
                    for (int nf = 0; nf < 8; nf++)
#pragma unroll
                        for (int e = 0; e < 4; e++)
                            mx[e >> 1] = fmaxf(mx[e >> 1], sacc[nf][e]);
                } else {
#pragma unroll
                    for (int nf = 0; nf < 8; nf++)
#pragma unroll
                        for (int e = 0; e < 4; e++) {
                            const int col = k0 + nf * 8 + (lane & 3) * 2 + (e & 1);
                            const int r = e >> 1;
                            if (col > qi0 + r * 8) sacc[nf][e] = -1e30f;
                            else mx[r] = fmaxf(mx[r], sacc[nf][e]);
                        }
                }
#pragma unroll
                for (int r = 0; r < 2; r++) {
                    mx[r] = fmaxf(mx[r], __shfl_xor_sync(0xffffffffu, mx[r], 1));
                    mx[r] = fmaxf(mx[r], __shfl_xor_sync(0xffffffffu, mx[r], 2));
                }
                float mn[2], corr[2], sum[2] = {0.f, 0.f};
#pragma unroll
                for (int r = 0; r < 2; r++) {
                    mn[r] = fmaxf(mrow[r], mx[r]);
                    corr[r] = ex2f(mrow[r] - mn[r]);
                    mrow[r] = mn[r];
                }
#pragma unroll
                for (int nf = 0; nf < 8; nf++)
#pragma unroll
                    for (int e = 0; e < 4; e++) {
                        const int r = e >> 1;
                        const float pv = ex2f(sacc[nf][e] - mn[r]);
                        sacc[nf][e] = pv;
                        sum[r] += pv;
                    }
#pragma unroll
                for (int r = 0; r < 2; r++) {
                    sum[r] += __shfl_xor_sync(0xffffffffu, sum[r], 1);
                    sum[r] += __shfl_xor_sync(0xffffffffu, sum[r], 2);
                    lrow[r] = lrow[r] * corr[r] + sum[r];
                }
#pragma unroll
                for (int nf = 0; nf < 8; nf++)
#pragma unroll
                    for (int e = 0; e < 4; e++) oacc[nf][e] *= corr[e >> 1];
                // ---- PV
#pragma unroll
                for (int ks = 0; ks < 4; ks++) {
                    uint32_t pf[4];
                    pf[0] = pack_f16(sacc[2 * ks][0], sacc[2 * ks][1]);
                    pf[1] = pack_f16(sacc[2 * ks][2], sacc[2 * ks][3]);
                    pf[2] = pack_f16(sacc[2 * ks + 1][0], sacc[2 * ks + 1][1]);
                    pf[3] = pack_f16(sacc[2 * ks + 1][2], sacc[2 * ks + 1][3]);
                    uint32_t vf[4][4];
#pragma unroll
                    for (int g = 0; g < 4; g++) {
                        const uint32_t rb = kvb + 9216 +
                            ((ks * 16 + (lane & 15)) * 72 + g * 16 + (lane >> 4) * 8) * 2;
                        ldm_x4_t(vf[g], rb);
                    }
#pragma unroll
                    for (int nf = 0; nf < 8; nf++) {
                        const int g = nf >> 1, o = (nf & 1) * 2;
                        uint32_t bf[2] = {vf[g][o], vf[g][o + 1]};
                        mma16816h(oacc[nf], pf, bf);
                    }
                }
            }
        }

        // write ao as fp16 (input of out-proj GEMM)
        const int bb = bh >> 3, h = bh & 7;
#pragma unroll
        for (int r = 0; r < 2; r++) {
            const float inv = 1.f / lrow[r];
            const int qi = qi0 + r * 8;
            const size_t rowoff = ((size_t)bb * SEQ + qi) * DMODEL + h * HDIM;
#pragma unroll
            for (int nf = 0; nf < 8; nf++) {
                const int hd = nf * 8 + (lane & 3) * 2;
                *reinterpret_cast<uint32_t*>(g_aof + rowoff + hd) =
                    pack_f16(oacc[nf][r * 2] * inv, oacc[nf][r * 2 + 1] * inv);
            }
        }
    }
}

// ---------------------------------------------------------------- launch
extern "C" void kernel_launch(void* const* d_in, const int* in_sizes, int n_in,
                              void* d_out, int out_size) {
    const float* x     = (const float*)d_in[0];
    const float* w_qkv = (const float*)d_in[1];
    const float* b_qkv = (const float*)d_in[2];
    const float* w_out = (const float*)d_in[3];
    const float* b_out = (const float*)d_in[4];
    float* out = (float*)d_out;

    __half *xf, *wqf, *wof, *aof;
    cudaGetSymbolAddress((void**)&xf, g_xf);
    cudaGetSymbolAddress((void**)&wqf, g_wqf);
    cudaGetSymbolAddress((void**)&wof, g_wof);
    cudaGetSymbolAddress((void**)&aof, g_aof);

    const int SMEM_GEMM = 3 * GSTG;           // 56832
    const int SMEM_ATT  = 18432 + 3 * 18432;  // 73728 (x2 CTAs = 147456 <= 228KB)
    cudaFuncSetAttribute(gemm_f16<0>, cudaFuncAttributeMaxDynamicSharedMemorySize, SMEM_GEMM);
    cudaFuncSetAttribute(gemm_f16<1>, cudaFuncAttributeMaxDynamicSharedMemorySize, SMEM_GEMM);
    cudaFuncSetAttribute(attn_mma,    cudaFuncAttributeMaxDynamicSharedMemorySize, SMEM_ATT);

    // fused pre-convert (x, w_qkv, w_out -> fp16)
    convert_all<<<(N4_TOT + 255) / 256, 256>>>(
        (const float4*)x, (const float4*)w_qkv, (const float4*)w_out);

    // 1) QKV projection -> q/k/v fp16 (Q pre-scaled by 0.125*log2e)
    gemm_f16<0><<<dim3(QKV_N / 128, MROWS / 128), 256, SMEM_GEMM>>>(
        xf, wqf, b_qkv, nullptr, QKV_N);
    // 2) causal attention (fp16, 2 CTAs/SM, balanced wave) -> g_aof
    attn_mma<<<dim3(16 / 2, BATCH * NHEAD), 256, SMEM_ATT>>>();
    // 3) output projection -> fp32 out
    gemm_f16<1><<<dim3(DMODEL / 128, MROWS / 128), 256, SMEM_GEMM>>>(
        aof, wof, b_out, out, DMODEL);
}

// round 14
// speedup vs baseline: 1.0401x; 1.0401x over previous
#include <cuda_runtime.h>
#include <cuda_fp16.h>
#include <cstdint>

// ---------------------------------------------------------------- constants
#define BATCH 4
#define SEQ   2048
#define DMODEL 512
#define NHEAD 8
#define HDIM  64
#define MROWS 8192
#define QKV_N 1536

// ---------------------------------------------------------------- scratch (fp16)
__device__ __half g_xf[(size_t)MROWS * DMODEL];
__device__ __half g_wqf[(size_t)DMODEL * QKV_N];
__device__ __half g_wof[(size_t)DMODEL * DMODEL];
__device__ __half g_qf[(size_t)BATCH * NHEAD * SEQ * HDIM];
__device__ __half g_kf[(size_t)BATCH * NHEAD * SEQ * HDIM];
__device__ __half g_vf[(size_t)BATCH * NHEAD * SEQ * HDIM];
__device__ __half g_aof[(size_t)MROWS * DMODEL];

// ---------------------------------------------------------------- helpers
__device__ __forceinline__ uint32_t smem_u32(const void* p) {
    uint32_t a;
    asm("{ .reg .u64 t; cvta.to.shared.u64 t, %1; cvt.u32.u64 %0, t; }"
        : "=r"(a) : "l"(p));
    return a;
}
__device__ __forceinline__ void ldm_x4(uint32_t* r, uint32_t addr) {
    asm volatile("ldmatrix.sync.aligned.m8n8.x4.shared.b16 {%0,%1,%2,%3}, [%4];"
                 : "=r"(r[0]), "=r"(r[1]), "=r"(r[2]), "=r"(r[3]) : "r"(addr));
}
__device__ __forceinline__ void ldm_x4_t(uint32_t* r, uint32_t addr) {
    asm volatile("ldmatrix.sync.aligned.m8n8.x4.trans.shared.b16 {%0,%1,%2,%3}, [%4];"
                 : "=r"(r[0]), "=r"(r[1]), "=r"(r[2]), "=r"(r[3]) : "r"(addr));
}
__device__ __forceinline__ void mma16816h(float* d, const uint32_t* a, const uint32_t* b) {
    asm volatile(
        "mma.sync.aligned.m16n8k16.row.col.f32.f16.f16.f32 "
        "{%0,%1,%2,%3}, {%4,%5,%6,%7}, {%8,%9}, {%0,%1,%2,%3};"
        : "+f"(d[0]), "+f"(d[1]), "+f"(d[2]), "+f"(d[3])
        : "r"(a[0]), "r"(a[1]), "r"(a[2]), "r"(a[3]), "r"(b[0]), "r"(b[1]));
}
__device__ __forceinline__ uint32_t pack_f16(float a, float b) {
    __half2 h = __floats2half2_rn(a, b);
    return *reinterpret_cast<uint32_t*>(&h);
}
__device__ __forceinline__ float ex2f(float x) {
    float r;
    asm("ex2.approx.f32 %0, %1;" : "=f"(r) : "f"(x));
    return r;
}

#define CP16(dst, src) \
    asm volatile("cp.async.cg.shared.global [%0], [%1], 16;" :: "r"(dst), "l"(src))
#define CP_COMMIT() asm volatile("cp.async.commit_group;" ::: "memory")
#define CP_WAIT(n)  asm volatile("cp.async.wait_group %0;" :: "n"(n) : "memory")

// Q scale with log2(e) folded in: scores come out in log2 domain.
#define QSCALE (0.125f * 1.4426950408889634f)

// ---------------------------------------------------------------- fused convert fp32 -> fp16
#define N4_X  (MROWS * DMODEL / 4)
#define N4_WQ (DMODEL * QKV_N / 4)
#define N4_WO (DMODEL * DMODEL / 4)
#define N4_TOT (N4_X + N4_WQ + N4_WO)
__global__ __launch_bounds__(256)
void convert_all(const float4* __restrict__ x, const float4* __restrict__ wq,
                 const float4* __restrict__ wo) {
    const int i = blockIdx.x * 256 + threadIdx.x;
    if (i >= N4_TOT) return;
    const float4* src;
    uint2* dst;
    int j = i;
    if (j < N4_X) { src = x; dst = (uint2*)g_xf; }
    else if ((j -= N4_X) < N4_WQ) { src = wq; dst = (uint2*)g_wqf; }
    else { j -= N4_WQ; src = wo; dst = (uint2*)g_wof; }
    float4 v = src[j];
    uint2 o;
    o.x = pack_f16(v.x, v.y);
    o.y = pack_f16(v.z, v.w);
    dst[j] = o;
}

// ---------------------------------------------------------------- GEMM (fp16 HMMA)
// BM=128 BN=128 BK=32, 8 warps (4m x 2n), warp tile 32x64. 3-stage cp.async.
// Stage (18944 B): A[128x40h]@0, B[32x136h]@10240.
#define GSTG 18944
template <int MODE>
__global__ __launch_bounds__(256, 2)
void gemm_f16(const __half* __restrict__ A, const __half* __restrict__ B,
              const float* __restrict__ bias, float* __restrict__ C, int N) {
    extern __shared__ char sm[];
    const uint32_t sbase = smem_u32(sm);
    const int tid = threadIdx.x, lane = tid & 31, w = tid >> 5;
    const int wm = w >> 1, wn = w & 1;
    const int m0 = blockIdx.y * 128, n0 = blockIdx.x * 128;

    float acc[2][8][4];
#pragma unroll
    for (int i = 0; i < 2; i++)
#pragma unroll
        for (int j = 0; j < 8; j++)
#pragma unroll
            for (int e = 0; e < 4; e++) acc[i][j][e] = 0.f;

    const int q0 = tid * 2;
    const int ar0 = q0 >> 2, ac0 = q0 & 3;
    const int ar1 = (q0 + 1) >> 2, ac1 = (q0 + 1) & 3;
    const int br0 = q0 >> 4, bc0 = q0 & 15;
    const int br1 = (q0 + 1) >> 4, bc1 = (q0 + 1) & 15;

    auto issue = [&](int kt) {
        const uint32_t base = sbase + (kt % 3) * GSTG;
        CP16(base + ar0 * 80 + ac0 * 16, A + (size_t)(m0 + ar0) * 512 + kt * 32 + ac0 * 8);
        CP16(base + ar1 * 80 + ac1 * 16, A + (size_t)(m0 + ar1) * 512 + kt * 32 + ac1 * 8);
        CP16(base + 10240 + br0 * 272 + bc0 * 16, B + (size_t)(kt * 32 + br0) * N + n0 + bc0 * 8);
        CP16(base + 10240 + br1 * 272 + bc1 * 16, B + (size_t)(kt * 32 + br1) * N + n0 + bc1 * 8);
        CP_COMMIT();
    };

    issue(0);
    issue(1);
    for (int kt = 0; kt < 16; kt++) {
        CP_WAIT(1);
        __syncthreads();
        if (kt + 2 < 16) issue(kt + 2);
        const uint32_t bA = sbase + (kt % 3) * GSTG;
#pragma unroll
        for (int ks = 0; ks < 2; ks++) {
            uint32_t ah[2][4];
#pragma unroll
            for (int mf = 0; mf < 2; mf++) {
                const uint32_t ra = bA +
                    ((wm * 32 + mf * 16 + (lane & 15)) * 40 + ks * 16 + (lane >> 4) * 8) * 2;
                ldm_x4(ah[mf], ra);
            }
            uint32_t bh[4][4];
#pragma unroll
            for (int g = 0; g < 4; g++) {
                const uint32_t rb = bA + 10240 +
                    ((ks * 16 + (lane & 15)) * 136 + wn * 64 + g * 16 + (lane >> 4) * 8) * 2;
                ldm_x4_t(bh[g], rb);
            }
#pragma unroll
            for (int mf = 0; mf < 2; mf++)
#pragma unroll
                for (int nf = 0; nf < 8; nf++) {
                    const int g = nf >> 1, o = (nf & 1) * 2;
                    uint32_t bf[2] = {bh[g][o], bh[g][o + 1]};
                    mma16816h(acc[mf][nf], ah[mf], bf);
                }
        }
    }

    // epilogue
#pragma unroll
    for (int mf = 0; mf < 2; mf++)
#pragma unroll
        for (int nf = 0; nf < 8; nf++) {
            const int col = n0 + wn * 64 + nf * 8 + (lane & 3) * 2;
            const float b0 = bias[col], b1 = bias[col + 1];
#pragma unroll
            for (int rr = 0; rr < 2; rr++) {
                const int row = m0 + wm * 32 + mf * 16 + (lane >> 2) + rr * 8;
                float v0 = acc[mf][nf][rr * 2] + b0;
                float v1 = acc[mf][nf][rr * 2 + 1] + b1;
                if (MODE == 0) {
                    const int part = col >> 9, ww = col & 511;
                    const int h = ww >> 6, hd = ww & 63;
                    const int bb = row >> 11, sidx = row & 2047;
                    if (part == 0) { v0 *= QSCALE; v1 *= QSCALE; }
                    __half* df = (part == 0) ? g_qf : (part == 1) ? g_kf : g_vf;
                    const size_t idx =
                        ((((size_t)bb * NHEAD + h) * SEQ) + sidx) * HDIM + hd;
                    *reinterpret_cast<uint32_t*>(df + idx) = pack_f16(v0, v1);
                } else {
                    *reinterpret_cast<float2*>(C + (size_t)row * N + col) =
                        make_float2(v0, v1);
                }
            }
        }
}

// ---------------------------------------------------------------- attention (fp16 HMMA)
// 512 threads (16 warps), q-block = 256 rows, grid (4, 32): CTA p -> {p, 7-p},
// 18 stage-iterations of 128 keys (two 64-key halves per sync).
// Triple-buffered 128-key KV ring, ONE __syncthreads per stage.
// Smem: Q@0 (256x72h = 36864 B); stage s @ 36864+s*36864:
//   K[128x72h]@+0 (18432 B), V[128x72h]@+18432. Total 147456 B.
__global__ __launch_bounds__(512)
void attn_mma() {
    extern __shared__ char sm[];
    const uint32_t sbase = smem_u32(sm);
    const int tid = threadIdx.x, lane = tid & 31, w = tid >> 5;
    const int p = blockIdx.x, bh = blockIdx.y;

    const size_t hbase = (size_t)bh * SEQ * HDIM;
    const int qlist[2] = {p, 7 - p};

    // load one 128-key stage (K + V), one commit group
    auto issueKV = [&](int st) {
        const uint32_t base = sbase + 36864 + (st % 3) * 36864;
        const int k0 = st * 128;
        const int row = tid >> 2, c2 = tid & 3;   // 128 rows x 4 chunk-pairs
        const size_t go = (size_t)(k0 + row) * 64 + c2 * 16;
        CP16(base + row * 144 + c2 * 32, g_kf + hbase + go);
        CP16(base + row * 144 + c2 * 32 + 16, g_kf + hbase + go + 8);
        CP16(base + 18432 + row * 144 + c2 * 32, g_vf + hbase + go);
        CP16(base + 18432 + row * 144 + c2 * 32 + 16, g_vf + hbase + go + 8);
        CP_COMMIT();
    };

    for (int qq = 0; qq < 2; qq++) {
        const int qb = qlist[qq];
        const __half* Qf = g_qf + hbase + (size_t)qb * 256 * HDIM;

        __syncthreads();   // guard Q smem rewrite vs previous qq readers
#pragma unroll
        for (int t = 0; t < 4; t++) {
            const int q = tid * 4 + t;
            const int row = q >> 3, c = q & 7;
            CP16(sbase + row * 144 + c * 16, Qf + (size_t)row * 64 + c * 8);
        }
        CP_COMMIT();

        const int nst = 2 * qb + 2;     // 128-key stages
        issueKV(0);

        float oacc[8][4];
#pragma unroll
        for (int j = 0; j < 8; j++)
#pragma unroll
            for (int e = 0; e < 4; e++) oacc[j][e] = 0.f;
        float mrow[2] = {-1e30f, -1e30f};
        float lrow[2] = {0.f, 0.f};
        const int qi0 = qb * 256 + w * 16 + (lane >> 2);

        for (int st = 0; st < nst; st++) {
            if (st + 1 < nst) { issueKV(st + 1); CP_WAIT(1); }
            else CP_WAIT(0);
            __syncthreads();   // single sync per 128-key stage
            const uint32_t stb = sbase + 36864 + (st % 3) * 36864;

#pragma unroll
            for (int half = 0; half < 2; half++) {
                const int k0 = st * 128 + half * 64;
                const uint32_t kvb = stb + half * 9216;   // 64-row offset within stage

                if (qb * 256 + w * 16 + 15 < k0) break;   // fully masked

                // ---- S = Q K^T (log2-domain scores)
                float sacc[8][4];
#pragma unroll
                for (int j = 0; j < 8; j++)
#pragma unroll
                    for (int e = 0; e < 4; e++) sacc[j][e] = 0.f;
#pragma unroll
                for (int ks = 0; ks < 4; ks++) {
                    uint32_t qf[4];
                    const uint32_t ra = sbase +
                        ((w * 16 + (lane & 15)) * 72 + ks * 16 + (lane >> 4) * 8) * 2;
                    ldm_x4(qf, ra);
                    uint32_t kf[4][4];
#pragma unroll
                    for (int g = 0; g < 4; g++) {
                        const uint32_t rb = kvb +
                            ((g * 16 + (lane & 15)) * 72 + ks * 16 + (lane >> 4) * 8) * 2;
                        ldm_x4(kf[g], rb);
                    }
#pragma unroll
                    for (int nf = 0; nf < 8; nf++) {
                        const int g = nf >> 1, o = nf & 1;
                        uint32_t bf[2] = {kf[g][o], kf[g][o + 2]};
                        mma16816h(sacc[nf], qf, bf);
                    }
                }
                // ---- online softmax (ex2-domain)
                float mx[2] = {-1e30f, -1e30f};
                if (k0 + 63 <= qi0) {
#pragma unroll
                    for (int nf = 0; nf < 8; nf++)
#pragma unroll
                        for (int e = 0; e < 4; e++)
                            mx[e >> 1] = fmaxf(mx[e >> 1], sacc[nf][e]);
                } else {
#pragma unroll
                    for (int nf = 0; nf < 8; nf++)
#pragma unroll
                        for (int e = 0; e < 4; e++) {
                            const int col = k0 + nf * 8 + (lane & 3) * 2 + (e & 1);
                            const int r = e >> 1;
                            if (col > qi0 + r * 8) sacc[nf][e] = -1e30f;
                            else mx[r] = fmaxf(mx[r], sacc[nf][e]);
                        }
                }
#pragma unroll
                for (int r = 0; r < 2; r++) {
                    mx[r] = fmaxf(mx[r], __shfl_xor_sync(0xffffffffu, mx[r], 1));
                    mx[r] = fmaxf(mx[r], __shfl_xor_sync(0xffffffffu, mx[r], 2));
                }
                float mn[2], corr[2], sum[2] = {0.f, 0.f};
#pragma unroll
                for (int r = 0; r < 2; r++) {
                    mn[r] = fmaxf(mrow[r], mx[r]);
                    corr[r] = ex2f(mrow[r] - mn[r]);
                    mrow[r] = mn[r];
                }
#pragma unroll
                for (int nf = 0; nf < 8; nf++)
#pragma unroll
                    for (int e = 0; e < 4; e++) {
                        const int r = e >> 1;
                        const float pv = ex2f(sacc[nf][e] - mn[r]);
                        sacc[nf][e] = pv;
                        sum[r] += pv;
                    }
#pragma unroll
                for (int r = 0; r < 2; r++) {
                    sum[r] += __shfl_xor_sync(0xffffffffu, sum[r], 1);
                    sum[r] += __shfl_xor_sync(0xffffffffu, sum[r], 2);
                    lrow[r] = lrow[r] * corr[r] + sum[r];
                }
#pragma unroll
                for (int nf = 0; nf < 8; nf++)
#pragma unroll
                    for (int e = 0; e < 4; e++) oacc[nf][e] *= corr[e >> 1];
                // ---- PV
#pragma unroll
                for (int ks = 0; ks < 4; ks++) {
                    uint32_t pf[4];
                    pf[0] = pack_f16(sacc[2 * ks][0], sacc[2 * ks][1]);
                    pf[1] = pack_f16(sacc[2 * ks][2], sacc[2 * ks][3]);
                    pf[2] = pack_f16(sacc[2 * ks + 1][0], sacc[2 * ks + 1][1]);
                    pf[3] = pack_f16(sacc[2 * ks + 1][2], sacc[2 * ks + 1][3]);
                    uint32_t vf[4][4];
#pragma unroll
                    for (int g = 0; g < 4; g++) {
                        const uint32_t rb = kvb + 18432 +
                            ((ks * 16 + (lane & 15)) * 72 + g * 16 + (lane >> 4) * 8) * 2;
                        ldm_x4_t(vf[g], rb);
                    }
#pragma unroll
                    for (int nf = 0; nf < 8; nf++) {
                        const int g = nf >> 1, o = (nf & 1) * 2;
                        uint32_t bf[2] = {vf[g][o], vf[g][o + 1]};
                        mma16816h(oacc[nf], pf, bf);
                    }
                }
            }
        }

        // write ao as fp16 (input of out-proj GEMM)
        const int bb = bh >> 3, h = bh & 7;
#pragma unroll
        for (int r = 0; r < 2; r++) {
            const float inv = 1.f / lrow[r];
            const int qi = qi0 + r * 8;
            const size_t rowoff = ((size_t)bb * SEQ + qi) * DMODEL + h * HDIM;
#pragma unroll
            for (int nf = 0; nf < 8; nf++) {
                const int hd = nf * 8 + (lane & 3) * 2;
                *reinterpret_cast<uint32_t*>(g_aof + rowoff + hd) =
                    pack_f16(oacc[nf][r * 2] * inv, oacc[nf][r * 2 + 1] * inv);
            }
        }
    }
}

// ---------------------------------------------------------------- launch
extern "C" void kernel_launch(void* const* d_in, const int* in_sizes, int n_in,
                              void* d_out, int out_size) {
    const float* x     = (const float*)d_in[0];
    const float* w_qkv = (const float*)d_in[1];
    const float* b_qkv = (const float*)d_in[2];
    const float* w_out = (const float*)d_in[3];
    const float* b_out = (const float*)d_in[4];
    float* out = (float*)d_out;

    __half *xf, *wqf, *wof, *aof;
    cudaGetSymbolAddress((void**)&xf, g_xf);
    cudaGetSymbolAddress((void**)&wqf, g_wqf);
    cudaGetSymbolAddress((void**)&wof, g_wof);
    cudaGetSymbolAddress((void**)&aof, g_aof);

    const int SMEM_GEMM = 3 * GSTG;            // 56832
    const int SMEM_ATT  = 36864 + 3 * 36864;   // 147456
    cudaFuncSetAttribute(gemm_f16<0>, cudaFuncAttributeMaxDynamicSharedMemorySize, SMEM_GEMM);
    cudaFuncSetAttribute(gemm_f16<1>, cudaFuncAttributeMaxDynamicSharedMemorySize, SMEM_GEMM);
    cudaFuncSetAttribute(attn_mma,    cudaFuncAttributeMaxDynamicSharedMemorySize, SMEM_ATT);

    // fused pre-convert (x, w_qkv, w_out -> fp16)
    convert_all<<<(N4_TOT + 255) / 256, 256>>>(
        (const float4*)x, (const float4*)w_qkv, (const float4*)w_out);

    // 1) QKV projection -> q/k/v fp16 (Q pre-scaled by 0.125*log2e)
    gemm_f16<0><<<dim3(QKV_N / 128, MROWS / 128), 256, SMEM_GEMM>>>(
        xf, wqf, b_qkv, nullptr, QKV_N);
    // 2) causal attention (fp16, 128-key stages, balanced wave) -> g_aof
    attn_mma<<<dim3(4, BATCH * NHEAD), 512, SMEM_ATT>>>();
    // 3) output projection -> fp32 out
    gemm_f16<1><<<dim3(DMODEL / 128, MROWS / 128), 256, SMEM_GEMM>>>(
        aof, wof, b_out, out, DMODEL);
}

// round 15
// speedup vs baseline: 1.0441x; 1.0038x over previous
#include <cuda_runtime.h>
#include <cuda_fp16.h>
#include <cstdint>

// ---------------------------------------------------------------- constants
#define BATCH 4
#define SEQ   2048
#define DMODEL 512
#define NHEAD 8
#define HDIM  64
#define MROWS 8192
#define QKV_N 1536

// ---------------------------------------------------------------- scratch (fp16)
__device__ __half g_xf[(size_t)MROWS * DMODEL];
__device__ __half g_wqf[(size_t)DMODEL * QKV_N];
__device__ __half g_wof[(size_t)DMODEL * DMODEL];
__device__ __half g_qf[(size_t)BATCH * NHEAD * SEQ * HDIM];
__device__ __half g_kf[(size_t)BATCH * NHEAD * SEQ * HDIM];
__device__ __half g_vf[(size_t)BATCH * NHEAD * SEQ * HDIM];
__device__ __half g_aof[(size_t)MROWS * DMODEL];

// ---------------------------------------------------------------- helpers
__device__ __forceinline__ uint32_t smem_u32(const void* p) {
    uint32_t a;
    asm("{ .reg .u64 t; cvta.to.shared.u64 t, %1; cvt.u32.u64 %0, t; }"
        : "=r"(a) : "l"(p));
    return a;
}
__device__ __forceinline__ void ldm_x4(uint32_t* r, uint32_t addr) {
    asm volatile("ldmatrix.sync.aligned.m8n8.x4.shared.b16 {%0,%1,%2,%3}, [%4];"
                 : "=r"(r[0]), "=r"(r[1]), "=r"(r[2]), "=r"(r[3]) : "r"(addr));
}
__device__ __forceinline__ void ldm_x4_t(uint32_t* r, uint32_t addr) {
    asm volatile("ldmatrix.sync.aligned.m8n8.x4.trans.shared.b16 {%0,%1,%2,%3}, [%4];"
                 : "=r"(r[0]), "=r"(r[1]), "=r"(r[2]), "=r"(r[3]) : "r"(addr));
}
__device__ __forceinline__ void mma16816h(float* d, const uint32_t* a, const uint32_t* b) {
    asm volatile(
        "mma.sync.aligned.m16n8k16.row.col.f32.f16.f16.f32 "
        "{%0,%1,%2,%3}, {%4,%5,%6,%7}, {%8,%9}, {%0,%1,%2,%3};"
        : "+f"(d[0]), "+f"(d[1]), "+f"(d[2]), "+f"(d[3])
        : "r"(a[0]), "r"(a[1]), "r"(a[2]), "r"(a[3]), "r"(b[0]), "r"(b[1]));
}
__device__ __forceinline__ uint32_t pack_f16(float a, float b) {
    __half2 h = __floats2half2_rn(a, b);
    return *reinterpret_cast<uint32_t*>(&h);
}
__device__ __forceinline__ float ex2f(float x) {
    float r;
    asm("ex2.approx.f32 %0, %1;" : "=f"(r) : "f"(x));
    return r;
}

#define CP16(dst, src) \
    asm volatile("cp.async.cg.shared.global [%0], [%1], 16;" :: "r"(dst), "l"(src))
#define CP_COMMIT() asm volatile("cp.async.commit_group;" ::: "memory")
#define CP_WAIT(n)  asm volatile("cp.async.wait_group %0;" :: "n"(n) : "memory")

// Q scale with log2(e) folded in: scores come out in log2 domain.
#define QSCALE (0.125f * 1.4426950408889634f)

// ---------------------------------------------------------------- fused convert fp32 -> fp16
#define N4_X  (MROWS * DMODEL / 4)
#define N4_WQ (DMODEL * QKV_N / 4)
#define N4_WO (DMODEL * DMODEL / 4)
#define N4_TOT (N4_X + N4_WQ + N4_WO)
__global__ __launch_bounds__(256)
void convert_all(const float4* __restrict__ x, const float4* __restrict__ wq,
                 const float4* __restrict__ wo) {
    const int i = blockIdx.x * 256 + threadIdx.x;
    if (i >= N4_TOT) return;
    const float4* src;
    uint2* dst;
    int j = i;
    if (j < N4_X) { src = x; dst = (uint2*)g_xf; }
    else if ((j -= N4_X) < N4_WQ) { src = wq; dst = (uint2*)g_wqf; }
    else { j -= N4_WQ; src = wo; dst = (uint2*)g_wof; }
    float4 v = src[j];
    uint2 o;
    o.x = pack_f16(v.x, v.y);
    o.y = pack_f16(v.z, v.w);
    dst[j] = o;
}

// ---------------------------------------------------------------- GEMM (fp16 HMMA)
// BM=128 BN=128 BK=32, 8 warps (4m x 2n), warp tile 32x64. 3-stage cp.async.
// Stage (18944 B): A[128x40h]@0, B[32x136h]@10240.
#define GSTG 18944
template <int MODE>
__global__ __launch_bounds__(256, 2)
void gemm_f16(const __half* __restrict__ A, const __half* __restrict__ B,
              const float* __restrict__ bias, float* __restrict__ C, int N) {
    extern __shared__ char sm[];
    const uint32_t sbase = smem_u32(sm);
    const int tid = threadIdx.x, lane = tid & 31, w = tid >> 5;
    const int wm = w >> 1, wn = w & 1;
    const int m0 = blockIdx.y * 128, n0 = blockIdx.x * 128;

    float acc[2][8][4];
#pragma unroll
    for (int i = 0; i < 2; i++)
#pragma unroll
        for (int j = 0; j < 8; j++)
#pragma unroll
            for (int e = 0; e < 4; e++) acc[i][j][e] = 0.f;

    const int q0 = tid * 2;
    const int ar0 = q0 >> 2, ac0 = q0 & 3;
    const int ar1 = (q0 + 1) >> 2, ac1 = (q0 + 1) & 3;
    const int br0 = q0 >> 4, bc0 = q0 & 15;
    const int br1 = (q0 + 1) >> 4, bc1 = (q0 + 1) & 15;

    auto issue = [&](int kt) {
        const uint32_t base = sbase + (kt % 3) * GSTG;
        CP16(base + ar0 * 80 + ac0 * 16, A + (size_t)(m0 + ar0) * 512 + kt * 32 + ac0 * 8);
        CP16(base + ar1 * 80 + ac1 * 16, A + (size_t)(m0 + ar1) * 512 + kt * 32 + ac1 * 8);
        CP16(base + 10240 + br0 * 272 + bc0 * 16, B + (size_t)(kt * 32 + br0) * N + n0 + bc0 * 8);
        CP16(base + 10240 + br1 * 272 + bc1 * 16, B + (size_t)(kt * 32 + br1) * N + n0 + bc1 * 8);
        CP_COMMIT();
    };

    issue(0);
    issue(1);
    for (int kt = 0; kt < 16; kt++) {
        CP_WAIT(1);
        __syncthreads();
        if (kt + 2 < 16) issue(kt + 2);
        const uint32_t bA = sbase + (kt % 3) * GSTG;
#pragma unroll
        for (int ks = 0; ks < 2; ks++) {
            uint32_t ah[2][4];
#pragma unroll
            for (int mf = 0; mf < 2; mf++) {
                const uint32_t ra = bA +
                    ((wm * 32 + mf * 16 + (lane & 15)) * 40 + ks * 16 + (lane >> 4) * 8) * 2;
                ldm_x4(ah[mf], ra);
            }
            uint32_t bh[4][4];
#pragma unroll
            for (int g = 0; g < 4; g++) {
                const uint32_t rb = bA + 10240 +
                    ((ks * 16 + (lane & 15)) * 136 + wn * 64 + g * 16 + (lane >> 4) * 8) * 2;
                ldm_x4_t(bh[g], rb);
            }
#pragma unroll
            for (int mf = 0; mf < 2; mf++)
#pragma unroll
                for (int nf = 0; nf < 8; nf++) {
                    const int g = nf >> 1, o = (nf & 1) * 2;
                    uint32_t bf[2] = {bh[g][o], bh[g][o + 1]};
                    mma16816h(acc[mf][nf], ah[mf], bf);
                }
        }
    }

    // epilogue
#pragma unroll
    for (int mf = 0; mf < 2; mf++)
#pragma unroll
        for (int nf = 0; nf < 8; nf++) {
            const int col = n0 + wn * 64 + nf * 8 + (lane & 3) * 2;
            const float b0 = bias[col], b1 = bias[col + 1];
#pragma unroll
            for (int rr = 0; rr < 2; rr++) {
                const int row = m0 + wm * 32 + mf * 16 + (lane >> 2) + rr * 8;
                float v0 = acc[mf][nf][rr * 2] + b0;
                float v1 = acc[mf][nf][rr * 2 + 1] + b1;
                if (MODE == 0) {
                    const int part = col >> 9, ww = col & 511;
                    const int h = ww >> 6, hd = ww & 63;
                    const int bb = row >> 11, sidx = row & 2047;
                    if (part == 0) { v0 *= QSCALE; v1 *= QSCALE; }
                    __half* df = (part == 0) ? g_qf : (part == 1) ? g_kf : g_vf;
                    const size_t idx =
                        ((((size_t)bb * NHEAD + h) * SEQ) + sidx) * HDIM + hd;
                    *reinterpret_cast<uint32_t*>(df + idx) = pack_f16(v0, v1);
                } else {
                    *reinterpret_cast<float2*>(C + (size_t)row * N + col) =
                        make_float2(v0, v1);
                }
            }
        }
}

// ---------------------------------------------------------------- attention (fp16 HMMA)
// 512 threads (16 warps), q-block = 256 rows, grid (4, 32): CTA p -> {p, 7-p},
// 128-key stages (two 64-key halves per sync), Q fragments register-cached.
// Triple-buffered 128-key KV ring, ONE __syncthreads per stage.
// Smem: Q@0 (256x72h = 36864 B); stage s @ 36864+s*36864:
//   K[128x72h]@+0 (18432 B), V[128x72h]@+18432. Total 147456 B.
__global__ __launch_bounds__(512)
void attn_mma() {
    extern __shared__ char sm[];
    const uint32_t sbase = smem_u32(sm);
    const int tid = threadIdx.x, lane = tid & 31, w = tid >> 5;
    const int p = blockIdx.x, bh = blockIdx.y;

    const size_t hbase = (size_t)bh * SEQ * HDIM;
    const int qlist[2] = {p, 7 - p};

    // load one 128-key stage (K + V), one commit group
    auto issueKV = [&](int st) {
        const uint32_t base = sbase + 36864 + (st % 3) * 36864;
        const int k0 = st * 128;
        const int row = tid >> 2, c2 = tid & 3;   // 128 rows x 4 chunk-pairs
        const size_t go = (size_t)(k0 + row) * 64 + c2 * 16;
        CP16(base + row * 144 + c2 * 32, g_kf + hbase + go);
        CP16(base + row * 144 + c2 * 32 + 16, g_kf + hbase + go + 8);
        CP16(base + 18432 + row * 144 + c2 * 32, g_vf + hbase + go);
        CP16(base + 18432 + row * 144 + c2 * 32 + 16, g_vf + hbase + go + 8);
        CP_COMMIT();
    };

    for (int qq = 0; qq < 2; qq++) {
        const int qb = qlist[qq];
        const __half* Qf = g_qf + hbase + (size_t)qb * 256 * HDIM;

        __syncthreads();   // guard Q smem + KV ring rewrite vs previous qq readers
#pragma unroll
        for (int t = 0; t < 4; t++) {
            const int q = tid * 4 + t;
            const int row = q >> 3, c = q & 7;
            CP16(sbase + row * 144 + c * 16, Qf + (size_t)row * 64 + c * 8);
        }
        CP_COMMIT();

        const int nst = 2 * qb + 2;     // 128-key stages
        issueKV(0);

        // ---- Q fragments -> registers (reused across all stages)
        CP_WAIT(1);        // Q group done (stage-0 KV may still be in flight)
        __syncthreads();
        uint32_t qfr[4][4];
#pragma unroll
        for (int ks = 0; ks < 4; ks++) {
            const uint32_t ra = sbase +
                ((w * 16 + (lane & 15)) * 72 + ks * 16 + (lane >> 4) * 8) * 2;
            ldm_x4(qfr[ks], ra);
        }

        float oacc[8][4];
#pragma unroll
        for (int j = 0; j < 8; j++)
#pragma unroll
            for (int e = 0; e < 4; e++) oacc[j][e] = 0.f;
        float mrow[2] = {-1e30f, -1e30f};
        float lrow[2] = {0.f, 0.f};
        const int qi0 = qb * 256 + w * 16 + (lane >> 2);

        for (int st = 0; st < nst; st++) {
            if (st + 1 < nst) { issueKV(st + 1); CP_WAIT(1); }
            else CP_WAIT(0);
            __syncthreads();   // single sync per 128-key stage
            const uint32_t stb = sbase + 36864 + (st % 3) * 36864;

#pragma unroll
            for (int half = 0; half < 2; half++) {
                const int k0 = st * 128 + half * 64;
                const uint32_t kvb = stb + half * 9216;

                if (qb * 256 + w * 16 + 15 < k0) break;   // fully masked

                // ---- S = Q K^T (log2-domain scores)
                float sacc[8][4];
#pragma unroll
                for (int j = 0; j < 8; j++)
#pragma unroll
                    for (int e = 0; e < 4; e++) sacc[j][e] = 0.f;
#pragma unroll
                for (int ks = 0; ks < 4; ks++) {
                    uint32_t kf[4][4];
#pragma unroll
                    for (int g = 0; g < 4; g++) {
                        const uint32_t rb = kvb +
                            ((g * 16 + (lane & 15)) * 72 + ks * 16 + (lane >> 4) * 8) * 2;
                        ldm_x4(kf[g], rb);
                    }
#pragma unroll
                    for (int nf = 0; nf < 8; nf++) {
                        const int g = nf >> 1, o = nf & 1;
                        uint32_t bf[2] = {kf[g][o], kf[g][o + 2]};
                        mma16816h(sacc[nf], qfr[ks], bf);
                    }
                }
                // ---- online softmax (ex2-domain)
                float mx[2] = {-1e30f, -1e30f};
                if (k0 + 63 <= qi0) {
#pragma unroll
                    for (int nf = 0; nf < 8; nf++)
#pragma unroll
                        for (int e = 0; e < 4; e++)
                            mx[e >> 1] = fmaxf(mx[e >> 1], sacc[nf][e]);
                } else {
#pragma unroll
                    for (int nf = 0; nf < 8; nf++)
#pragma unroll
                        for (int e = 0; e < 4; e++) {
                            const int col = k0 + nf * 8 + (lane & 3) * 2 + (e & 1);
                            const int r = e >> 1;
                            if (col > qi0 + r * 8) sacc[nf][e] = -1e30f;
                            else mx[r] = fmaxf(mx[r], sacc[nf][e]);
                        }
                }
#pragma unroll
                for (int r = 0; r < 2; r++) {
                    mx[r] = fmaxf(mx[r], __shfl_xor_sync(0xffffffffu, mx[r], 1));
                    mx[r] = fmaxf(mx[r], __shfl_xor_sync(0xffffffffu, mx[r], 2));
                }
                float mn[2], corr[2], sum[2] = {0.f, 0.f};
#pragma unroll
                for (int r = 0; r < 2; r++) {
                    mn[r] = fmaxf(mrow[r], mx[r]);
                    corr[r] = ex2f(mrow[r] - mn[r]);
                    mrow[r] = mn[r];
                }
#pragma unroll
                for (int nf = 0; nf < 8; nf++)
#pragma unroll
                    for (int e = 0; e < 4; e++) {
                        const int r = e >> 1;
                        const float pv = ex2f(sacc[nf][e] - mn[r]);
                        sacc[nf][e] = pv;
                        sum[r] += pv;
                    }
#pragma unroll
                for (int r = 0; r < 2; r++) {
                    sum[r] += __shfl_xor_sync(0xffffffffu, sum[r], 1);
                    sum[r] += __shfl_xor_sync(0xffffffffu, sum[r], 2);
                    lrow[r] = lrow[r] * corr[r] + sum[r];
                }
#pragma unroll
                for (int nf = 0; nf < 8; nf++)
#pragma unroll
                    for (int e = 0; e < 4; e++) oacc[nf][e] *= corr[e >> 1];
                // ---- PV
#pragma unroll
                for (int ks = 0; ks < 4; ks++) {
                    uint32_t pf[4];
                    pf[0] = pack_f16(sacc[2 * ks][0], sacc[2 * ks][1]);
                    pf[1] = pack_f16(sacc[2 * ks][2], sacc[2 * ks][3]);
                    pf[2] = pack_f16(sacc[2 * ks + 1][0], sacc[2 * ks + 1][1]);
                    pf[3] = pack_f16(sacc[2 * ks + 1][2], sacc[2 * ks + 1][3]);
                    uint32_t vf[4][4];
#pragma unroll
                    for (int g = 0; g < 4; g++) {
                        const uint32_t rb = kvb + 18432 +
                            ((ks * 16 + (lane & 15)) * 72 + g * 16 + (lane >> 4) * 8) * 2;
                        ldm_x4_t(vf[g], rb);
                    }
#pragma unroll
                    for (int nf = 0; nf < 8; nf++) {
                        const int g = nf >> 1, o = (nf & 1) * 2;
                        uint32_t bf[2] = {vf[g][o], vf[g][o + 1]};
                        mma16816h(oacc[nf], pf, bf);
                    }
                }
            }
        }

        // write ao as fp16 (input of out-proj GEMM)
        const int bb = bh >> 3, h = bh & 7;
#pragma unroll
        for (int r = 0; r < 2; r++) {
            const float inv = 1.f / lrow[r];
            const int qi = qi0 + r * 8;
            const size_t rowoff = ((size_t)bb * SEQ + qi) * DMODEL + h * HDIM;
#pragma unroll
            for (int nf = 0; nf < 8; nf++) {
                const int hd = nf * 8 + (lane & 3) * 2;
                *reinterpret_cast<uint32_t*>(g_aof + rowoff + hd) =
                    pack_f16(oacc[nf][r * 2] * inv, oacc[nf][r * 2 + 1] * inv);
            }
        }
    }
}

// ---------------------------------------------------------------- launch
extern "C" void kernel_launch(void* const* d_in, const int* in_sizes, int n_in,
                              void* d_out, int out_size) {
    const float* x     = (const float*)d_in[0];
    const float* w_qkv = (const float*)d_in[1];
    const float* b_qkv = (const float*)d_in[2];
    const float* w_out = (const float*)d_in[3];
    const float* b_out = (const float*)d_in[4];
    float* out = (float*)d_out;

    __half *xf, *wqf, *wof, *aof;
    cudaGetSymbolAddress((void**)&xf, g_xf);
    cudaGetSymbolAddress((void**)&wqf, g_wqf);
    cudaGetSymbolAddress((void**)&wof, g_wof);
    cudaGetSymbolAddress((void**)&aof, g_aof);

    const int SMEM_GEMM = 3 * GSTG;            // 56832
    const int SMEM_ATT  = 36864 + 3 * 36864;   // 147456
    cudaFuncSetAttribute(gemm_f16<0>, cudaFuncAttributeMaxDynamicSharedMemorySize, SMEM_GEMM);
    cudaFuncSetAttribute(gemm_f16<1>, cudaFuncAttributeMaxDynamicSharedMemorySize, SMEM_GEMM);
    cudaFuncSetAttribute(attn_mma,    cudaFuncAttributeMaxDynamicSharedMemorySize, SMEM_ATT);

    // fused pre-convert (x, w_qkv, w_out -> fp16)
    convert_all<<<(N4_TOT + 255) / 256, 256>>>(
        (const float4*)x, (const float4*)w_qkv, (const float4*)w_out);

    // 1) QKV projection -> q/k/v fp16 (Q pre-scaled by 0.125*log2e)
    gemm_f16<0><<<dim3(QKV_N / 128, MROWS / 128), 256, SMEM_GEMM>>>(
        xf, wqf, b_qkv, nullptr, QKV_N);
    // 2) causal attention (fp16, Q reg-cached, 128-key stages) -> g_aof
    attn_mma<<<dim3(4, BATCH * NHEAD), 512, SMEM_ATT>>>();
    // 3) output projection -> fp32 out
    gemm_f16<1><<<dim3(DMODEL / 128, MROWS / 128), 256, SMEM_GEMM>>>(
        aof, wof, b_out, out, DMODEL);
}

// round 16
// speedup vs baseline: 1.0558x; 1.0112x over previous
#include <cuda_runtime.h>
#include <cuda_fp16.h>
#include <cstdint>

// ---------------------------------------------------------------- constants
#define BATCH 4
#define SEQ   2048
#define DMODEL 512
#define NHEAD 8
#define HDIM  64
#define MROWS 8192
#define QKV_N 1536

// ---------------------------------------------------------------- scratch (fp16)
__device__ __half g_xf[(size_t)MROWS * DMODEL];
__device__ __half g_wqf[(size_t)DMODEL * QKV_N];
__device__ __half g_wof[(size_t)DMODEL * DMODEL];
__device__ __half g_qf[(size_t)BATCH * NHEAD * SEQ * HDIM];
__device__ __half g_kf[(size_t)BATCH * NHEAD * SEQ * HDIM];
__device__ __half g_vf[(size_t)BATCH * NHEAD * SEQ * HDIM];
__device__ __half g_aof[(size_t)MROWS * DMODEL];

// ---------------------------------------------------------------- helpers
__device__ __forceinline__ uint32_t smem_u32(const void* p) {
    uint32_t a;
    asm("{ .reg .u64 t; cvta.to.shared.u64 t, %1; cvt.u32.u64 %0, t; }"
        : "=r"(a) : "l"(p));
    return a;
}
__device__ __forceinline__ void ldm_x4(uint32_t* r, uint32_t addr) {
    asm volatile("ldmatrix.sync.aligned.m8n8.x4.shared.b16 {%0,%1,%2,%3}, [%4];"
                 : "=r"(r[0]), "=r"(r[1]), "=r"(r[2]), "=r"(r[3]) : "r"(addr));
}
__device__ __forceinline__ void ldm_x4_t(uint32_t* r, uint32_t addr) {
    asm volatile("ldmatrix.sync.aligned.m8n8.x4.trans.shared.b16 {%0,%1,%2,%3}, [%4];"
                 : "=r"(r[0]), "=r"(r[1]), "=r"(r[2]), "=r"(r[3]) : "r"(addr));
}
__device__ __forceinline__ void mma16816h(float* d, const uint32_t* a, const uint32_t* b) {
    asm volatile(
        "mma.sync.aligned.m16n8k16.row.col.f32.f16.f16.f32 "
        "{%0,%1,%2,%3}, {%4,%5,%6,%7}, {%8,%9}, {%0,%1,%2,%3};"
        : "+f"(d[0]), "+f"(d[1]), "+f"(d[2]), "+f"(d[3])
        : "r"(a[0]), "r"(a[1]), "r"(a[2]), "r"(a[3]), "r"(b[0]), "r"(b[1]));
}
__device__ __forceinline__ uint32_t pack_f16(float a, float b) {
    __half2 h = __floats2half2_rn(a, b);
    return *reinterpret_cast<uint32_t*>(&h);
}
__device__ __forceinline__ float ex2f(float x) {
    float r;
    asm("ex2.approx.f32 %0, %1;" : "=f"(r) : "f"(x));
    return r;
}
__device__ __forceinline__ uint32_t h2ex2(uint32_t x) {
    uint32_t r;
    asm("ex2.approx.f16x2 %0, %1;" : "=r"(r) : "r"(x));
    return r;
}

#define CP16(dst, src) \
    asm volatile("cp.async.cg.shared.global [%0], [%1], 16;" :: "r"(dst), "l"(src))
#define CP_COMMIT() asm volatile("cp.async.commit_group;" ::: "memory")
#define CP_WAIT(n)  asm volatile("cp.async.wait_group %0;" :: "n"(n) : "memory")

// Q scale with log2(e) folded in: scores come out in log2 domain.
#define QSCALE (0.125f * 1.4426950408889634f)

// ---------------------------------------------------------------- fused convert fp32 -> fp16
#define N4_X  (MROWS * DMODEL / 4)
#define N4_WQ (DMODEL * QKV_N / 4)
#define N4_WO (DMODEL * DMODEL / 4)
#define N4_TOT (N4_X + N4_WQ + N4_WO)
__global__ __launch_bounds__(256)
void convert_all(const float4* __restrict__ x, const float4* __restrict__ wq,
                 const float4* __restrict__ wo) {
    const int i = blockIdx.x * 256 + threadIdx.x;
    if (i >= N4_TOT) return;
    const float4* src;
    uint2* dst;
    int j = i;
    if (j < N4_X) { src = x; dst = (uint2*)g_xf; }
    else if ((j -= N4_X) < N4_WQ) { src = wq; dst = (uint2*)g_wqf; }
    else { j -= N4_WQ; src = wo; dst = (uint2*)g_wof; }
    float4 v = src[j];
    uint2 o;
    o.x = pack_f16(v.x, v.y);
    o.y = pack_f16(v.z, v.w);
    dst[j] = o;
}

// ---------------------------------------------------------------- GEMM (fp16 HMMA)
// BM=128 BN=128 BK=32, 8 warps (4m x 2n), warp tile 32x64. 3-stage cp.async.
// Stage (18944 B): A[128x40h]@0, B[32x136h]@10240.
#define GSTG 18944
template <int MODE>
__global__ __launch_bounds__(256, 2)
void gemm_f16(const __half* __restrict__ A, const __half* __restrict__ B,
              const float* __restrict__ bias, float* __restrict__ C, int N) {
    extern __shared__ char sm[];
    const uint32_t sbase = smem_u32(sm);
    const int tid = threadIdx.x, lane = tid & 31, w = tid >> 5;
    const int wm = w >> 1, wn = w & 1;
    const int m0 = blockIdx.y * 128, n0 = blockIdx.x * 128;

    float acc[2][8][4];
#pragma unroll
    for (int i = 0; i < 2; i++)
#pragma unroll
        for (int j = 0; j < 8; j++)
#pragma unroll
            for (int e = 0; e < 4; e++) acc[i][j][e] = 0.f;

    const int q0 = tid * 2;
    const int ar0 = q0 >> 2, ac0 = q0 & 3;
    const int ar1 = (q0 + 1) >> 2, ac1 = (q0 + 1) & 3;
    const int br0 = q0 >> 4, bc0 = q0 & 15;
    const int br1 = (q0 + 1) >> 4, bc1 = (q0 + 1) & 15;

    auto issue = [&](int kt) {
        const uint32_t base = sbase + (kt % 3) * GSTG;
        CP16(base + ar0 * 80 + ac0 * 16, A + (size_t)(m0 + ar0) * 512 + kt * 32 + ac0 * 8);
        CP16(base + ar1 * 80 + ac1 * 16, A + (size_t)(m0 + ar1) * 512 + kt * 32 + ac1 * 8);
        CP16(base + 10240 + br0 * 272 + bc0 * 16, B + (size_t)(kt * 32 + br0) * N + n0 + bc0 * 8);
        CP16(base + 10240 + br1 * 272 + bc1 * 16, B + (size_t)(kt * 32 + br1) * N + n0 + bc1 * 8);
        CP_COMMIT();
    };

    issue(0);
    issue(1);
    for (int kt = 0; kt < 16; kt++) {
        CP_WAIT(1);
        __syncthreads();
        if (kt + 2 < 16) issue(kt + 2);
        const uint32_t bA = sbase + (kt % 3) * GSTG;
#pragma unroll
        for (int ks = 0; ks < 2; ks++) {
            uint32_t ah[2][4];
#pragma unroll
            for (int mf = 0; mf < 2; mf++) {
                const uint32_t ra = bA +
                    ((wm * 32 + mf * 16 + (lane & 15)) * 40 + ks * 16 + (lane >> 4) * 8) * 2;
                ldm_x4(ah[mf], ra);
            }
            uint32_t bh[4][4];
#pragma unroll
            for (int g = 0; g < 4; g++) {
                const uint32_t rb = bA + 10240 +
                    ((ks * 16 + (lane & 15)) * 136 + wn * 64 + g * 16 + (lane >> 4) * 8) * 2;
                ldm_x4_t(bh[g], rb);
            }
#pragma unroll
            for (int mf = 0; mf < 2; mf++)
#pragma unroll
                for (int nf = 0; nf < 8; nf++) {
                    const int g = nf >> 1, o = (nf & 1) * 2;
                    uint32_t bf[2] = {bh[g][o], bh[g][o + 1]};
                    mma16816h(acc[mf][nf], ah[mf], bf);
                }
        }
    }

    // epilogue
#pragma unroll
    for (int mf = 0; mf < 2; mf++)
#pragma unroll
        for (int nf = 0; nf < 8; nf++) {
            const int col = n0 + wn * 64 + nf * 8 + (lane & 3) * 2;
            const float b0 = bias[col], b1 = bias[col + 1];
#pragma unroll
            for (int rr = 0; rr < 2; rr++) {
                const int row = m0 + wm * 32 + mf * 16 + (lane >> 2) + rr * 8;
                float v0 = acc[mf][nf][rr * 2] + b0;
                float v1 = acc[mf][nf][rr * 2 + 1] + b1;
                if (MODE == 0) {
                    const int part = col >> 9, ww = col & 511;
                    const int h = ww >> 6, hd = ww & 63;
                    const int bb = row >> 11, sidx = row & 2047;
                    if (part == 0) { v0 *= QSCALE; v1 *= QSCALE; }
                    __half* df = (part == 0) ? g_qf : (part == 1) ? g_kf : g_vf;
                    const size_t idx =
                        ((((size_t)bb * NHEAD + h) * SEQ) + sidx) * HDIM + hd;
                    *reinterpret_cast<uint32_t*>(df + idx) = pack_f16(v0, v1);
                } else {
                    *reinterpret_cast<float2*>(C + (size_t)row * N + col) =
                        make_float2(v0, v1);
                }
            }
        }
}

// ---------------------------------------------------------------- attention (fp16 HMMA)
// 512 threads (16 warps), q-block = 256 rows, grid (4, 32): CTA p -> {p, 7-p},
// 128-key stages (two 64-key halves per sync), Q fragments register-cached,
// f16x2 ex2 softmax (P fragments produced directly), rescale-skip.
// Smem: Q@0 (256x72h = 36864 B); stage s @ 36864+s*36864:
//   K[128x72h]@+0 (18432 B), V[128x72h]@+18432. Total 147456 B.
__global__ __launch_bounds__(512)
void attn_mma() {
    extern __shared__ char sm[];
    const uint32_t sbase = smem_u32(sm);
    const int tid = threadIdx.x, lane = tid & 31, w = tid >> 5;
    const int p = blockIdx.x, bh = blockIdx.y;

    const size_t hbase = (size_t)bh * SEQ * HDIM;
    const int qlist[2] = {p, 7 - p};

    auto issueKV = [&](int st) {
        const uint32_t base = sbase + 36864 + (st % 3) * 36864;
        const int k0 = st * 128;
        const int row = tid >> 2, c2 = tid & 3;
        const size_t go = (size_t)(k0 + row) * 64 + c2 * 16;
        CP16(base + row * 144 + c2 * 32, g_kf + hbase + go);
        CP16(base + row * 144 + c2 * 32 + 16, g_kf + hbase + go + 8);
        CP16(base + 18432 + row * 144 + c2 * 32, g_vf + hbase + go);
        CP16(base + 18432 + row * 144 + c2 * 32 + 16, g_vf + hbase + go + 8);
        CP_COMMIT();
    };

    for (int qq = 0; qq < 2; qq++) {
        const int qb = qlist[qq];
        const __half* Qf = g_qf + hbase + (size_t)qb * 256 * HDIM;

        __syncthreads();   // guard Q smem + KV ring rewrite vs previous qq readers
#pragma unroll
        for (int t = 0; t < 4; t++) {
            const int q = tid * 4 + t;
            const int row = q >> 3, c = q & 7;
            CP16(sbase + row * 144 + c * 16, Qf + (size_t)row * 64 + c * 8);
        }
        CP_COMMIT();

        const int nst = 2 * qb + 2;
        issueKV(0);

        // Q fragments -> registers (reused across all stages)
        CP_WAIT(1);
        __syncthreads();
        uint32_t qfr[4][4];
#pragma unroll
        for (int ks = 0; ks < 4; ks++) {
            const uint32_t ra = sbase +
                ((w * 16 + (lane & 15)) * 72 + ks * 16 + (lane >> 4) * 8) * 2;
            ldm_x4(qfr[ks], ra);
        }

        float oacc[8][4];
#pragma unroll
        for (int j = 0; j < 8; j++)
#pragma unroll
            for (int e = 0; e < 4; e++) oacc[j][e] = 0.f;
        float mrow[2] = {-1e30f, -1e30f};
        float lrow[2] = {0.f, 0.f};
        const int qi0 = qb * 256 + w * 16 + (lane >> 2);

        for (int st = 0; st < nst; st++) {
            if (st + 1 < nst) { issueKV(st + 1); CP_WAIT(1); }
            else CP_WAIT(0);
            __syncthreads();
            const uint32_t stb = sbase + 36864 + (st % 3) * 36864;

#pragma unroll
            for (int half = 0; half < 2; half++) {
                const int k0 = st * 128 + half * 64;
                const uint32_t kvb = stb + half * 9216;

                if (qb * 256 + w * 16 + 15 < k0) break;

                // ---- S = Q K^T (log2-domain scores)
                float sacc[8][4];
#pragma unroll
                for (int j = 0; j < 8; j++)
#pragma unroll
                    for (int e = 0; e < 4; e++) sacc[j][e] = 0.f;
#pragma unroll
                for (int ks = 0; ks < 4; ks++) {
                    uint32_t kf[4][4];
#pragma unroll
                    for (int g = 0; g < 4; g++) {
                        const uint32_t rb = kvb +
                            ((g * 16 + (lane & 15)) * 72 + ks * 16 + (lane >> 4) * 8) * 2;
                        ldm_x4(kf[g], rb);
                    }
#pragma unroll
                    for (int nf = 0; nf < 8; nf++) {
                        const int g = nf >> 1, o = nf & 1;
                        uint32_t bf[2] = {kf[g][o], kf[g][o + 2]};
                        mma16816h(sacc[nf], qfr[ks], bf);
                    }
                }
                // ---- online softmax (f16x2 ex2)
                float mx[2] = {-1e30f, -1e30f};
                if (k0 + 63 <= qi0) {
#pragma unroll
                    for (int nf = 0; nf < 8; nf++)
#pragma unroll
                        for (int e = 0; e < 4; e++)
                            mx[e >> 1] = fmaxf(mx[e >> 1], sacc[nf][e]);
                } else {
#pragma unroll
                    for (int nf = 0; nf < 8; nf++)
#pragma unroll
                        for (int e = 0; e < 4; e++) {
                            const int col = k0 + nf * 8 + (lane & 3) * 2 + (e & 1);
                            const int r = e >> 1;
                            if (col > qi0 + r * 8) sacc[nf][e] = -1e30f;
                            else mx[r] = fmaxf(mx[r], sacc[nf][e]);
                        }
                }
#pragma unroll
                for (int r = 0; r < 2; r++) {
                    mx[r] = fmaxf(mx[r], __shfl_xor_sync(0xffffffffu, mx[r], 1));
                    mx[r] = fmaxf(mx[r], __shfl_xor_sync(0xffffffffu, mx[r], 2));
                }
                const float om0 = mrow[0], om1 = mrow[1];
                float mn[2], corr[2];
#pragma unroll
                for (int r = 0; r < 2; r++) {
                    mn[r] = fmaxf(mrow[r], mx[r]);
                    corr[r] = ex2f(mrow[r] - mn[r]);
                    mrow[r] = mn[r];
                }
                // p = 2^(s-mn) via ex2.approx.f16x2 -> ready-packed P fragments
                uint32_t pfr[8][2];
                float sum[2] = {0.f, 0.f};
#pragma unroll
                for (int nf = 0; nf < 8; nf++) {
                    const uint32_t e01 = h2ex2(
                        pack_f16(sacc[nf][0] - mn[0], sacc[nf][1] - mn[0]));
                    const uint32_t e23 = h2ex2(
                        pack_f16(sacc[nf][2] - mn[1], sacc[nf][3] - mn[1]));
                    pfr[nf][0] = e01;
                    pfr[nf][1] = e23;
                    const float2 f01 = __half22float2(*reinterpret_cast<const __half2*>(&e01));
                    const float2 f23 = __half22float2(*reinterpret_cast<const __half2*>(&e23));
                    sum[0] += f01.x + f01.y;
                    sum[1] += f23.x + f23.y;
                }
#pragma unroll
                for (int r = 0; r < 2; r++) {
                    sum[r] += __shfl_xor_sync(0xffffffffu, sum[r], 1);
                    sum[r] += __shfl_xor_sync(0xffffffffu, sum[r], 2);
                    lrow[r] = lrow[r] * corr[r] + sum[r];
                }
                // rescale only if some lane's max changed (warp-uniform skip)
                const unsigned changed = __ballot_sync(0xffffffffu,
                    (mn[0] != om0) | (mn[1] != om1));
                if (changed) {
#pragma unroll
                    for (int nf = 0; nf < 8; nf++)
#pragma unroll
                        for (int e = 0; e < 4; e++) oacc[nf][e] *= corr[e >> 1];
                }
                // ---- PV
#pragma unroll
                for (int ks = 0; ks < 4; ks++) {
                    uint32_t pf[4] = {pfr[2 * ks][0], pfr[2 * ks][1],
                                      pfr[2 * ks + 1][0], pfr[2 * ks + 1][1]};
                    uint32_t vf[4][4];
#pragma unroll
                    for (int g = 0; g < 4; g++) {
                        const uint32_t rb = kvb + 18432 +
                            ((ks * 16 + (lane & 15)) * 72 + g * 16 + (lane >> 4) * 8) * 2;
                        ldm_x4_t(vf[g], rb);
                    }
#pragma unroll
                    for (int nf = 0; nf < 8; nf++) {
                        const int g = nf >> 1, o = (nf & 1) * 2;
                        uint32_t bf[2] = {vf[g][o], vf[g][o + 1]};
                        mma16816h(oacc[nf], pf, bf);
                    }
                }
            }
        }

        // write ao as fp16 (input of out-proj GEMM)
        const int bb = bh >> 3, h = bh & 7;
#pragma unroll
        for (int r = 0; r < 2; r++) {
            const float inv = 1.f / lrow[r];
            const int qi = qi0 + r * 8;
            const size_t rowoff = ((size_t)bb * SEQ + qi) * DMODEL + h * HDIM;
#pragma unroll
            for (int nf = 0; nf < 8; nf++) {
                const int hd = nf * 8 + (lane & 3) * 2;
                *reinterpret_cast<uint32_t*>(g_aof + rowoff + hd) =
                    pack_f16(oacc[nf][r * 2] * inv, oacc[nf][r * 2 + 1] * inv);
            }
        }
    }
}

// ---------------------------------------------------------------- launch
extern "C" void kernel_launch(void* const* d_in, const int* in_sizes, int n_in,
                              void* d_out, int out_size) {
    const float* x     = (const float*)d_in[0];
    const float* w_qkv = (const float*)d_in[1];
    const float* b_qkv = (const float*)d_in[2];
    const float* w_out = (const float*)d_in[3];
    const float* b_out = (const float*)d_in[4];
    float* out = (float*)d_out;

    __half *xf, *wqf, *wof, *aof;
    cudaGetSymbolAddress((void**)&xf, g_xf);
    cudaGetSymbolAddress((void**)&wqf, g_wqf);
    cudaGetSymbolAddress((void**)&wof, g_wof);
    cudaGetSymbolAddress((void**)&aof, g_aof);

    const int SMEM_GEMM = 3 * GSTG;            // 56832
    const int SMEM_ATT  = 36864 + 3 * 36864;   // 147456
    cudaFuncSetAttribute(gemm_f16<0>, cudaFuncAttributeMaxDynamicSharedMemorySize, SMEM_GEMM);
    cudaFuncSetAttribute(gemm_f16<1>, cudaFuncAttributeMaxDynamicSharedMemorySize, SMEM_GEMM);
    cudaFuncSetAttribute(attn_mma,    cudaFuncAttributeMaxDynamicSharedMemorySize, SMEM_ATT);

    // fused pre-convert (x, w_qkv, w_out -> fp16)
    convert_all<<<(N4_TOT + 255) / 256, 256>>>(
        (const float4*)x, (const float4*)w_qkv, (const float4*)w_out);

    // 1) QKV projection -> q/k/v fp16 (Q pre-scaled by 0.125*log2e)
    gemm_f16<0><<<dim3(QKV_N / 128, MROWS / 128), 256, SMEM_GEMM>>>(
        xf, wqf, b_qkv, nullptr, QKV_N);
    // 2) causal attention (fp16, f16x2 softmax, Q reg-cached) -> g_aof
    attn_mma<<<dim3(4, BATCH * NHEAD), 512, SMEM_ATT>>>();
    // 3) output projection -> fp32 out
    gemm_f16<1><<<dim3(DMODEL / 128, MROWS / 128), 256, SMEM_GEMM>>>(
        aof, wof, b_out, out, DMODEL);
}